// round 6
// baseline (speedup 1.0000x reference)
#include <cuda_runtime.h>

// Fused filtered-lrelu: coalesced x load -> up-H (f32x2 packed phases) ->
// per-column up-V + lrelu + down-V fused in registers (f32x2 over column
// pairs) -> down-H. x: [1024,130,130] f32 -> out: [1024,128,128] f32.

typedef unsigned long long u64;

#define IH 130
#define IW 130
#define OW 128
#define XP 44      // x tile stride (42x44)
#define TP 78      // t tile stride (42 rows x 74 cols)
#define WP 76      // w tile stride (32 rows x 74 cols), mult of 4
#define NTHREADS 256

__device__ __forceinline__ u64 pk2(float x, float y) {
    u64 r; asm("mov.b64 %0,{%1,%2};" : "=l"(r) : "f"(x), "f"(y)); return r;
}
__device__ __forceinline__ float2 unpk(u64 a) {
    float2 r; asm("mov.b64 {%0,%1},%2;" : "=f"(r.x), "=f"(r.y) : "l"(a)); return r;
}
__device__ __forceinline__ u64 ffma2(u64 a, u64 b, u64 c) {
    u64 d; asm("fma.rn.f32x2 %0,%1,%2,%3;" : "=l"(d) : "l"(a), "l"(b), "l"(c)); return d;
}
__device__ __forceinline__ u64 fmul2(u64 a, u64 b) {
    u64 d; asm("mul.rn.f32x2 %0,%1,%2;" : "=l"(d) : "l"(a), "l"(b)); return d;
}

// 12-tap symmetric down filter (scalar), taps e0..e5 mirrored:
#define DN(v0,v1,v2,v3,v4,v5,v6,v7,v8,v9,v10,v11) \
    fmaf(e0,(v11), fmaf(e1,(v10), fmaf(e2,(v9), fmaf(e3,(v8), fmaf(e4,(v7), \
    fmaf(e5,(v6),  fmaf(e5,(v5),  fmaf(e4,(v4), fmaf(e3,(v3), fmaf(e2,(v2), \
    fmaf(e1,(v1),  e0*(v0))))))))))))

__global__ __launch_bounds__(NTHREADS)
void flrelu_fused_kernel(const float* __restrict__ x,
                         const float* __restrict__ fup,
                         const float* __restrict__ fdn,
                         float* __restrict__ out)
{
    __shared__ __align__(16) float t[42 * TP];   // 13.1 KB
    __shared__ __align__(16) float S2[32 * WP];  //  9.7 KB: x tile, then w tile
    float* Xs = S2;                               // 42x44 = 1848 floats (< 2432)
    float* w  = S2;                               // 32x76, written after Xs dies

    const float g0 = fup[0] * 2.0f, g1 = fup[1] * 2.0f, g2 = fup[2] * 2.0f,
                g3 = fup[3] * 2.0f, g4 = fup[4] * 2.0f, g5 = fup[5] * 2.0f;
    const float e0 = fdn[0], e1 = fdn[1], e2 = fdn[2],
                e3 = fdn[3], e4 = fdn[4], e5 = fdn[5];

    const int tile = blockIdx.x;
    const int ch   = blockIdx.y;
    const int m0   = (tile >> 2) * 32;
    const int n0   = (tile & 3) * 32;
    const int tid  = threadIdx.x;

    // ---- Stage 0: coalesced load of x tile [42 x 42] (stride 44), zero-padded.
    {
        const float* xc = x + (size_t)ch * IH * IW;
#pragma unroll
        for (int i = 0; i < 8; i++) {
            int idx = tid + i * NTHREADS;
            if (idx < 42 * XP) {
                int r = idx / XP, c = idx - r * XP;
                int gr = m0 - 4 + r, gc = n0 - 4 + c;
                float v = 0.0f;
                if ((unsigned)gr < IH && (unsigned)gc < IW) v = xc[gr * IW + gc];
                Xs[idx] = v;
            }
        }
    }
    __syncthreads();

    // ---- Stage A: horizontal 2x-up, (even,odd) phases packed as f32x2.
    // 42 rows x 6 segments; thread (r,s) -> 7 output pairs from Xs window.
    if (tid < 252) {
        const int r = tid / 6, s = tid - 6 * (tid / 6);
        float xa[14];
#pragma unroll
        for (int i = 0; i < 7; i++) {
            float2 v = *reinterpret_cast<const float2*>(&Xs[r * XP + 6 * s + 2 * i]);
            xa[2 * i] = v.x; xa[2 * i + 1] = v.y;
        }
        u64 xd[12];
#pragma unroll
        for (int k = 0; k < 12; k++) xd[k] = pk2(xa[k], xa[k]);
        // (E,O) taps per window position: E=[g1,g3,g5,g4,g2,g0], O=[g0,g2,g4,g5,g3,g1]
        const u64 P0 = pk2(g1, g0), P1 = pk2(g3, g2), P2 = pk2(g5, g4),
                  P3 = pk2(g4, g5), P4 = pk2(g2, g3), P5 = pk2(g0, g1);
#pragma unroll
        for (int k = 0; k < 7; k++) {
            u64 r2 = fmul2(P0, xd[k]);
            r2 = ffma2(P1, xd[k + 1], r2);
            r2 = ffma2(P2, xd[k + 2], r2);
            r2 = ffma2(P3, xd[k + 3], r2);
            r2 = ffma2(P4, xd[k + 4], r2);
            r2 = ffma2(P5, xd[k + 5], r2);
            *reinterpret_cast<u64*>(&t[r * TP + 12 * s + 2 * k]) = r2;
        }
    }
    __syncthreads();

    // ---- Stage B: per-column-pair vertical up + lrelu + down-V, f32x2 packed.
    // 37 col-pairs x 4 row-segments (8 outputs each). z never touches smem.
    if (tid < 148) {
        const int jp  = tid % 37;
        const int seg = tid / 37;
        const int mb  = seg << 3;                 // 0,8,16,24
        // tap dups
        const u64 GD0 = pk2(g1, g1), GD1 = pk2(g3, g3), GD2 = pk2(g5, g5),
                  GD3 = pk2(g4, g4), GD4 = pk2(g2, g2), GD5 = pk2(g0, g0);
        const u64 ED0 = pk2(e0, e0), ED1 = pk2(e1, e1), ED2 = pk2(e2, e2),
                  ED3 = pk2(e3, e3), ED4 = pk2(e4, e4), ED5 = pk2(e5, e5);
        u64 win[18];
        const float* tc = t + mb * TP + 2 * jp;
#pragma unroll
        for (int i = 0; i < 18; i++)
            win[i] = *reinterpret_cast<const u64*>(&tc[i * TP]);
        u64 acc0 = 0, acc1 = 0, acc2 = 0, acc3 = 0, acc4 = 0, acc5 = 0;
#pragma unroll
        for (int k = 0; k < 13; k++) {
            // even phase: taps GD0..GD5 fwd; odd phase: reversed
            u64 ze = fmul2(GD0, win[k]);
            ze = ffma2(GD1, win[k + 1], ze);
            ze = ffma2(GD2, win[k + 2], ze);
            ze = ffma2(GD3, win[k + 3], ze);
            ze = ffma2(GD4, win[k + 4], ze);
            ze = ffma2(GD5, win[k + 5], ze);
            u64 zo = fmul2(GD5, win[k]);
            zo = ffma2(GD4, win[k + 1], zo);
            zo = ffma2(GD3, win[k + 2], zo);
            zo = ffma2(GD2, win[k + 3], zo);
            zo = ffma2(GD1, win[k + 4], zo);
            zo = ffma2(GD0, win[k + 5], zo);
            // leaky relu: max(v, 0.01v) per half (FMNMX -> alu pipe)
            float2 a = unpk(ze), b = unpk(zo);
            a.x = fmaxf(a.x, 0.01f * a.x); a.y = fmaxf(a.y, 0.01f * a.y);
            b.x = fmaxf(b.x, 0.01f * b.x); b.y = fmaxf(b.y, 0.01f * b.y);
            ze = pk2(a.x, a.y); zo = pk2(b.x, b.y);
            // down-V rolling accumulators
            acc0 = ffma2(ED1, ze, ffma2(ED0, zo, acc0));
            acc1 = ffma2(ED3, ze, ffma2(ED2, zo, acc1));
            acc2 = ffma2(ED5, ze, ffma2(ED4, zo, acc2));
            acc3 = ffma2(ED4, ze, ffma2(ED5, zo, acc3));
            acc4 = ffma2(ED2, ze, ffma2(ED3, zo, acc4));
            acc5 = ffma2(ED0, ze, fmul2(ED1, zo));
            if (k >= 5)
                *reinterpret_cast<u64*>(&w[(mb + k - 5) * WP + 2 * jp]) = acc0;
            acc0 = acc1; acc1 = acc2; acc2 = acc3; acc3 = acc4; acc4 = acc5;
        }
    }
    __syncthreads();

    // ---- Stage C: horizontal down + store. Warp s owns col-seg s (conflict-
    // free LDS.128); thread (m, s) -> 8 outputs of row m from w[m][16s..16s+25].
    if (tid < 128) {
        const int s = tid >> 5, m = tid & 31;
        const float4* wr = reinterpret_cast<const float4*>(&w[m * WP + 16 * s]);
        float v[28];
#pragma unroll
        for (int i = 0; i < 7; i++) {
            float4 q = wr[i];
            v[4 * i] = q.x; v[4 * i + 1] = q.y; v[4 * i + 2] = q.z; v[4 * i + 3] = q.w;
        }
        float o[8];
#pragma unroll
        for (int q = 0; q < 8; q++)
            o[q] = DN(v[2*q],v[2*q+1],v[2*q+2],v[2*q+3],v[2*q+4],v[2*q+5],
                      v[2*q+6],v[2*q+7],v[2*q+8],v[2*q+9],v[2*q+10],v[2*q+11]);
        float* od = out + (size_t)ch * OW * OW + (size_t)(m0 + m) * OW + n0 + 8 * s;
        *reinterpret_cast<float4*>(od)     = make_float4(o[0], o[1], o[2], o[3]);
        *reinterpret_cast<float4*>(od + 4) = make_float4(o[4], o[5], o[6], o[7]);
    }
}

extern "C" void kernel_launch(void* const* d_in, const int* in_sizes, int n_in,
                              void* d_out, int out_size) {
    const float* x   = (const float*)d_in[0];
    const float* fup = (const float*)d_in[1];
    const float* fdn = (const float*)d_in[2];
    float* out = (float*)d_out;
    dim3 grid(16, 1024);
    flrelu_fused_kernel<<<grid, NTHREADS>>>(x, fup, fdn, out);
}

// round 7
// speedup vs baseline: 1.1936x; 1.1936x over previous
#include <cuda_runtime.h>

// Fused filtered-lrelu: coalesced x-tile load -> up-H -> per-column
// (up-V + lrelu + down-V fused in registers) -> down-H. All-scalar math
// (R3 structure) + smem-staged x (R4's one good change).
// x: [1024,130,130] f32 -> out: [1024,128,128] f32, 12-tap symmetric filters.

#define IH 130
#define IW 130
#define OW 128
#define XP 44      // x tile stride (42 rows x 42 cols, stride 44)
#define TP 78      // t tile stride (42 rows x 74 cols)
#define WP 76      // w tile stride (32 rows x 74 cols), mult of 4
#define NTHREADS 256

// up-pair from 6-sample window, 6 unique symmetric taps g0..g5:
//   even phase taps [fu1,fu3,fu5,fu7,fu9,fu11] = [g1,g3,g5,g4,g2,g0]
//   odd  phase taps [fu0,fu2,fu4,fu6,fu8,fu10] = [g0,g2,g4,g5,g3,g1]
#define UP_E(w0,w1,w2,w3,w4,w5) \
    fmaf(g0,(w5), fmaf(g2,(w4), fmaf(g4,(w3), fmaf(g5,(w2), fmaf(g3,(w1), g1*(w0))))))
#define UP_O(w0,w1,w2,w3,w4,w5) \
    fmaf(g1,(w5), fmaf(g3,(w4), fmaf(g5,(w3), fmaf(g4,(w2), fmaf(g2,(w1), g0*(w0))))))
// 12-tap symmetric down filter over v0..v11:
#define DN(v0,v1,v2,v3,v4,v5,v6,v7,v8,v9,v10,v11) \
    fmaf(e0,(v11), fmaf(e1,(v10), fmaf(e2,(v9), fmaf(e3,(v8), fmaf(e4,(v7), \
    fmaf(e5,(v6),  fmaf(e5,(v5),  fmaf(e4,(v4), fmaf(e3,(v3), fmaf(e2,(v2), \
    fmaf(e1,(v1),  e0*(v0))))))))))))

__global__ __launch_bounds__(NTHREADS)
void flrelu_fused_kernel(const float* __restrict__ x,
                         const float* __restrict__ fup,
                         const float* __restrict__ fdn,
                         float* __restrict__ out)
{
    __shared__ __align__(16) float t[42 * TP];   // 13.1 KB
    __shared__ __align__(16) float S2[32 * WP];  //  9.7 KB (2432 floats)
    float* Xs = S2;                              // 42*44 = 1848 floats, dies at stage A end
    float* w  = S2;                              // 32*76, written in stage B

    const float g0 = fup[0] * 2.0f, g1 = fup[1] * 2.0f, g2 = fup[2] * 2.0f,
                g3 = fup[3] * 2.0f, g4 = fup[4] * 2.0f, g5 = fup[5] * 2.0f;
    const float e0 = fdn[0], e1 = fdn[1], e2 = fdn[2],
                e3 = fdn[3], e4 = fdn[4], e5 = fdn[5];

    const int tile = blockIdx.x;
    const int ch   = blockIdx.y;
    const int m0   = (tile >> 2) * 32;
    const int n0   = (tile & 3) * 32;
    const int tid  = threadIdx.x;

    // ---- Stage 0: coalesced load of x tile [42 x 42] (stride 44), zero-padded.
    {
        const float* xc = x + (size_t)ch * IH * IW;
#pragma unroll
        for (int i = 0; i < 8; i++) {
            int idx = tid + i * NTHREADS;
            if (idx < 42 * XP) {
                int r = idx / XP, c = idx - r * XP;
                int gr = m0 - 4 + r, gc = n0 - 4 + c;
                float v = 0.0f;
                if ((unsigned)gr < IH && (unsigned)gc < IW) v = xc[gr * IW + gc];
                Xs[idx] = v;
            }
        }
    }
    __syncthreads();

    // ---- Stage A: horizontal 2x-up from smem. 42 rows x 6 segments; thread
    // (r,s) reads Xs[r][6s..6s+13] (7 float2 LDS) -> 7 output pairs -> t.
    if (tid < 252) {
        const int r = tid / 6, s = tid - 6 * (tid / 6);
        float xa[14];
#pragma unroll
        for (int i = 0; i < 7; i++) {
            float2 v = *reinterpret_cast<const float2*>(&Xs[r * XP + 6 * s + 2 * i]);
            xa[2 * i] = v.x; xa[2 * i + 1] = v.y;
        }
        float2* trow = reinterpret_cast<float2*>(t + r * TP) + 6 * s;
#pragma unroll
        for (int k = 0; k < 7; k++) {
            trow[k] = make_float2(UP_E(xa[k],xa[k+1],xa[k+2],xa[k+3],xa[k+4],xa[k+5]),
                                  UP_O(xa[k],xa[k+1],xa[k+2],xa[k+3],xa[k+4],xa[k+5]));
        }
    }
    __syncthreads();

    // ---- Stage B: per-column vertical up + lrelu + down-V fused in registers.
    // 74 cols x 2 row-segments (16 outputs each); z never touches smem.
    if (tid < 148) {
        const int seg = (tid >= 74) ? 1 : 0;
        const int j   = tid - 74 * seg;
        const int mb  = seg << 4;                  // 0 or 16
        const float* tc = t + mb * TP + j;
        float win[26];
#pragma unroll
        for (int i = 0; i < 26; i++) win[i] = tc[i * TP];
        float acc0 = 0.f, acc1 = 0.f, acc2 = 0.f, acc3 = 0.f, acc4 = 0.f, acc5 = 0.f;
        float* wc = w + j;
#pragma unroll
        for (int k = 0; k < 21; k++) {
            float ze = UP_E(win[k],win[k+1],win[k+2],win[k+3],win[k+4],win[k+5]);
            float zo = UP_O(win[k],win[k+1],win[k+2],win[k+3],win[k+4],win[k+5]);
            ze = (ze >= 0.f) ? ze : 0.01f * ze;
            zo = (zo >= 0.f) ? zo : 0.01f * zo;
            acc0 = fmaf(e1, ze, fmaf(e0, zo, acc0));
            acc1 = fmaf(e3, ze, fmaf(e2, zo, acc1));
            acc2 = fmaf(e5, ze, fmaf(e4, zo, acc2));
            acc3 = fmaf(e4, ze, fmaf(e5, zo, acc3));
            acc4 = fmaf(e2, ze, fmaf(e3, zo, acc4));
            acc5 = fmaf(e0, ze, fmaf(e1, zo, acc5));
            if (k >= 5) wc[(mb + k - 5) * WP] = acc0;
            acc0 = acc1; acc1 = acc2; acc2 = acc3; acc3 = acc4; acc4 = acc5;
            acc5 = 0.f;
        }
    }
    __syncthreads();

    // ---- Stage C: horizontal down + store. Thread (m, s) computes out cols
    // 4s..4s+3 of row m from w[m][8s..8s+17] (5 float4 LDS), float4 store.
    {
        const int m = tid >> 3, s = tid & 7;
        const float4* wr = reinterpret_cast<const float4*>(w + m * WP) + 2 * s;
        float4 q0 = wr[0], q1 = wr[1], q2 = wr[2], q3 = wr[3], q4 = wr[4];
        float v0=q0.x,v1=q0.y,v2=q0.z,v3=q0.w,
              v4=q1.x,v5=q1.y,v6=q1.z,v7=q1.w,
              v8=q2.x,v9=q2.y,v10=q2.z,v11=q2.w,
              v12=q3.x,v13=q3.y,v14=q3.z,v15=q3.w,
              v16=q4.x,v17=q4.y;
        float o0 = DN(v0,v1,v2,v3,v4,v5,v6,v7,v8,v9,v10,v11);
        float o1 = DN(v2,v3,v4,v5,v6,v7,v8,v9,v10,v11,v12,v13);
        float o2 = DN(v4,v5,v6,v7,v8,v9,v10,v11,v12,v13,v14,v15);
        float o3 = DN(v6,v7,v8,v9,v10,v11,v12,v13,v14,v15,v16,v17);
        float* od = out + (size_t)ch * OW * OW + (size_t)(m0 + m) * OW + n0 + 4 * s;
        *reinterpret_cast<float4*>(od) = make_float4(o0, o1, o2, o3);
    }
}

extern "C" void kernel_launch(void* const* d_in, const int* in_sizes, int n_in,
                              void* d_out, int out_size) {
    const float* x   = (const float*)d_in[0];
    const float* fup = (const float*)d_in[1];
    const float* fdn = (const float*)d_in[2];
    float* out = (float*)d_out;
    dim3 grid(16, 1024);
    flrelu_fused_kernel<<<grid, NTHREADS>>>(x, fup, fdn, out);
}

// round 8
// speedup vs baseline: 1.3314x; 1.1154x over previous
#include <cuda_runtime.h>

// Fused filtered-lrelu: up-H from gmem -> per-column (up-V + lrelu + down-V
// fused in registers) -> down-H. R3 structure + dead-update peeling + cheap
// lrelu + cheap predication. x: [1024,130,130] f32 -> out: [1024,128,128] f32.

#define IH 130
#define IW 130
#define OW 128
#define TP 78      // t tile stride (42 rows x 74 cols)
#define WP 76      // w tile stride (32 rows x 74 cols), mult of 4
#define NTHREADS 256

// up-pair from 6-sample window, 6 unique symmetric taps g0..g5:
//   even phase taps [fu1,fu3,fu5,fu7,fu9,fu11] = [g1,g3,g5,g4,g2,g0]
//   odd  phase taps [fu0,fu2,fu4,fu6,fu8,fu10] = [g0,g2,g4,g5,g3,g1]
#define UP_E(w0,w1,w2,w3,w4,w5) \
    fmaf(g0,(w5), fmaf(g2,(w4), fmaf(g4,(w3), fmaf(g5,(w2), fmaf(g3,(w1), g1*(w0))))))
#define UP_O(w0,w1,w2,w3,w4,w5) \
    fmaf(g1,(w5), fmaf(g3,(w4), fmaf(g5,(w3), fmaf(g4,(w2), fmaf(g2,(w1), g0*(w0))))))
// 12-tap symmetric down filter over v0..v11:
#define DN(v0,v1,v2,v3,v4,v5,v6,v7,v8,v9,v10,v11) \
    fmaf(e0,(v11), fmaf(e1,(v10), fmaf(e2,(v9), fmaf(e3,(v8), fmaf(e4,(v7), \
    fmaf(e5,(v6),  fmaf(e5,(v5),  fmaf(e4,(v4), fmaf(e3,(v3), fmaf(e2,(v2), \
    fmaf(e1,(v1),  e0*(v0))))))))))))

__global__ __launch_bounds__(NTHREADS)
void flrelu_fused_kernel(const float* __restrict__ x,
                         const float* __restrict__ fup,
                         const float* __restrict__ fdn,
                         float* __restrict__ out)
{
    __shared__ __align__(16) float t[42 * TP];   // 13.1 KB
    __shared__ __align__(16) float w[32 * WP];   //  9.7 KB

    const float g0 = fup[0] * 2.0f, g1 = fup[1] * 2.0f, g2 = fup[2] * 2.0f,
                g3 = fup[3] * 2.0f, g4 = fup[4] * 2.0f, g5 = fup[5] * 2.0f;
    const float e0 = fdn[0], e1 = fdn[1], e2 = fdn[2],
                e3 = fdn[3], e4 = fdn[4], e5 = fdn[5];

    const int tile = blockIdx.x;
    const int ch   = blockIdx.y;
    const int m0   = (tile >> 2) * 32;
    const int n0   = (tile & 3) * 32;
    const int tid  = threadIdx.x;

    // ---- Stage A: horizontal 2x-up straight from gmem. 42 rows x 6 segs;
    // thread (r,s) reads x[r][6s-4 .. 6s+8], writes t cols 12s..12s+13.
    if (tid < 252) {
        const int r = tid / 6, s = tid - 6 * (tid / 6);
        const int gr  = m0 - 4 + r;
        const int gc0 = n0 - 4 + 6 * s;
        const bool rok = (unsigned)gr < (unsigned)IH;
        const float* xrow = x + (size_t)ch * IH * IW + gr * IW + gc0;
        float xa[13];
        if (n0 == 32 || n0 == 64) {
            // interior columns: only the row predicate matters
#pragma unroll
            for (int k = 0; k < 13; k++) xa[k] = rok ? xrow[k] : 0.0f;
        } else {
#pragma unroll
            for (int k = 0; k < 13; k++) {
                bool ok = rok && ((unsigned)(gc0 + k) < (unsigned)IW);
                xa[k] = ok ? xrow[k] : 0.0f;
            }
        }
        float2* trow = reinterpret_cast<float2*>(t + r * TP) + 6 * s;
#pragma unroll
        for (int k = 0; k < 7; k++) {
            trow[k] = make_float2(UP_E(xa[k],xa[k+1],xa[k+2],xa[k+3],xa[k+4],xa[k+5]),
                                  UP_O(xa[k],xa[k+1],xa[k+2],xa[k+3],xa[k+4],xa[k+5]));
        }
    }
    __syncthreads();

    // ---- Stage B: per-column vertical up + lrelu + down-V fused in registers.
    // 74 cols x 2 row-segments (16 outputs each). An update to acc_i at step k
    // feeds the output stored at step k+i; guard 5 <= k+i <= 20 (compile-time).
    if (tid < 148) {
        const int seg = (tid >= 74) ? 1 : 0;
        const int j   = tid - 74 * seg;
        const int mb  = seg << 4;                  // 0 or 16
        const float* tc = t + mb * TP + j;
        float win[26];
#pragma unroll
        for (int i = 0; i < 26; i++) win[i] = tc[i * TP];
        float acc0 = 0.f, acc1 = 0.f, acc2 = 0.f, acc3 = 0.f, acc4 = 0.f, acc5 = 0.f;
        float* wc = w + j;
#pragma unroll
        for (int k = 0; k < 21; k++) {
            float ze = UP_E(win[k],win[k+1],win[k+2],win[k+3],win[k+4],win[k+5]);
            float zo = UP_O(win[k],win[k+1],win[k+2],win[k+3],win[k+4],win[k+5]);
            ze = fmaxf(ze, 0.01f * ze);            // lrelu (exact)
            zo = fmaxf(zo, 0.01f * zo);
            if (k >= 5)            acc0 = fmaf(e1, ze, fmaf(e0, zo, acc0));
            if (k >= 4 && k <= 19) acc1 = fmaf(e3, ze, fmaf(e2, zo, acc1));
            if (k >= 3 && k <= 18) acc2 = fmaf(e5, ze, fmaf(e4, zo, acc2));
            if (k >= 2 && k <= 17) acc3 = fmaf(e4, ze, fmaf(e5, zo, acc3));
            if (k >= 1 && k <= 16) acc4 = fmaf(e2, ze, fmaf(e3, zo, acc4));
            if (k <= 15)           acc5 = fmaf(e0, ze, e1 * zo);
            if (k >= 5) wc[(mb + k - 5) * WP] = acc0;
            acc0 = acc1; acc1 = acc2; acc2 = acc3; acc3 = acc4; acc4 = acc5;
        }
    }
    __syncthreads();

    // ---- Stage C: horizontal down + store. Thread (m, s) computes out cols
    // 4s..4s+3 of row m from w[m][8s..8s+17] (5 float4 LDS), float4 store.
    {
        const int m = tid >> 3, s = tid & 7;
        const float4* wr = reinterpret_cast<const float4*>(w + m * WP) + 2 * s;
        float4 q0 = wr[0], q1 = wr[1], q2 = wr[2], q3 = wr[3], q4 = wr[4];
        float v0=q0.x,v1=q0.y,v2=q0.z,v3=q0.w,
              v4=q1.x,v5=q1.y,v6=q1.z,v7=q1.w,
              v8=q2.x,v9=q2.y,v10=q2.z,v11=q2.w,
              v12=q3.x,v13=q3.y,v14=q3.z,v15=q3.w,
              v16=q4.x,v17=q4.y;
        float o0 = DN(v0,v1,v2,v3,v4,v5,v6,v7,v8,v9,v10,v11);
        float o1 = DN(v2,v3,v4,v5,v6,v7,v8,v9,v10,v11,v12,v13);
        float o2 = DN(v4,v5,v6,v7,v8,v9,v10,v11,v12,v13,v14,v15);
        float o3 = DN(v6,v7,v8,v9,v10,v11,v12,v13,v14,v15,v16,v17);
        float* od = out + (size_t)ch * OW * OW + (size_t)(m0 + m) * OW + n0 + 4 * s;
        *reinterpret_cast<float4*>(od) = make_float4(o0, o1, o2, o3);
    }
}

extern "C" void kernel_launch(void* const* d_in, const int* in_sizes, int n_in,
                              void* d_out, int out_size) {
    const float* x   = (const float*)d_in[0];
    const float* fup = (const float*)d_in[1];
    const float* fdn = (const float*)d_in[2];
    float* out = (float*)d_out;
    dim3 grid(16, 1024);
    flrelu_fused_kernel<<<grid, NTHREADS>>>(x, fup, fdn, out);
}

// round 10
// speedup vs baseline: 1.3937x; 1.0468x over previous
#include <cuda_runtime.h>

// Fused filtered-lrelu: up-H from gmem (vector LDG.64) -> per-column
// (up-V + lrelu + down-V fused in registers) -> down-H.
// x: [1024,130,130] f32 -> out: [1024,128,128] f32, 12-tap symmetric filters.

#define IH 130
#define IW 130
#define OW 128
#define TP 80      // t tile stride (42 rows x 74 cols), mult of 4 for STS.128
#define WP 76      // w tile stride (32 rows x 74 cols), mult of 4
#define NTHREADS 256

// up-pair from 6-sample window, 6 unique symmetric taps g0..g5:
//   even phase taps [fu1,fu3,fu5,fu7,fu9,fu11] = [g1,g3,g5,g4,g2,g0]
//   odd  phase taps [fu0,fu2,fu4,fu6,fu8,fu10] = [g0,g2,g4,g5,g3,g1]
#define UP_E(w0,w1,w2,w3,w4,w5) \
    fmaf(g0,(w5), fmaf(g2,(w4), fmaf(g4,(w3), fmaf(g5,(w2), fmaf(g3,(w1), g1*(w0))))))
#define UP_O(w0,w1,w2,w3,w4,w5) \
    fmaf(g1,(w5), fmaf(g3,(w4), fmaf(g5,(w3), fmaf(g4,(w2), fmaf(g2,(w1), g0*(w0))))))
// 12-tap symmetric down filter over v0..v11:
#define DN(v0,v1,v2,v3,v4,v5,v6,v7,v8,v9,v10,v11) \
    fmaf(e0,(v11), fmaf(e1,(v10), fmaf(e2,(v9), fmaf(e3,(v8), fmaf(e4,(v7), \
    fmaf(e5,(v6),  fmaf(e5,(v5),  fmaf(e4,(v4), fmaf(e3,(v3), fmaf(e2,(v2), \
    fmaf(e1,(v1),  e0*(v0))))))))))))

__global__ __launch_bounds__(NTHREADS)
void flrelu_fused_kernel(const float* __restrict__ x,
                         const float* __restrict__ fup,
                         const float* __restrict__ fdn,
                         float* __restrict__ out)
{
    __shared__ __align__(16) float t[42 * TP];   // 13.4 KB
    __shared__ __align__(16) float w[32 * WP];   //  9.7 KB

    const float g0 = fup[0] * 2.0f, g1 = fup[1] * 2.0f, g2 = fup[2] * 2.0f,
                g3 = fup[3] * 2.0f, g4 = fup[4] * 2.0f, g5 = fup[5] * 2.0f;
    const float e0 = fdn[0], e1 = fdn[1], e2 = fdn[2],
                e3 = fdn[3], e4 = fdn[4], e5 = fdn[5];

    const int tile = blockIdx.x;
    const int ch   = blockIdx.y;
    const int m0   = (tile >> 2) * 32;
    const int n0   = (tile & 3) * 32;
    const int tid  = threadIdx.x;

    // ---- Stage A: horizontal 2x-up from gmem with float2 loads.
    // 42 rows x 6 segs; window start gc0 = n0-4+6s is always EVEN, and with
    // IW=130 (even) every float2 pair is fully in-bounds or fully out, so
    // 7 predicated LDG.64 cover the 13-sample window (xa[13] used).
    if (tid < 252) {
        const int r = tid / 6, s = tid - 6 * (tid / 6);
        const int gr  = m0 - 4 + r;
        const int gc0 = n0 - 4 + 6 * s;            // even
        const bool rok = (unsigned)gr < (unsigned)IH;
        const float2* xrow2 = reinterpret_cast<const float2*>(
            x + (size_t)ch * IH * IW + (size_t)gr * IW + gc0);
        float xa[14];
        if (n0 == 32 || n0 == 64) {                // interior: row predicate only
#pragma unroll
            for (int p = 0; p < 7; p++) {
                float2 v = rok ? xrow2[p] : make_float2(0.f, 0.f);
                xa[2 * p] = v.x; xa[2 * p + 1] = v.y;
            }
        } else {
#pragma unroll
            for (int p = 0; p < 7; p++) {
                bool ok = rok && ((unsigned)(gc0 + 2 * p) < (unsigned)IW);
                float2 v = ok ? xrow2[p] : make_float2(0.f, 0.f);
                xa[2 * p] = v.x; xa[2 * p + 1] = v.y;
            }
        }
        // 7 output pairs -> 3 STS.128 + 1 STS.64 (base 16B-aligned: TP,12s mult of 4)
        float2 o[7];
#pragma unroll
        for (int k = 0; k < 7; k++) {
            o[k] = make_float2(UP_E(xa[k],xa[k+1],xa[k+2],xa[k+3],xa[k+4],xa[k+5]),
                               UP_O(xa[k],xa[k+1],xa[k+2],xa[k+3],xa[k+4],xa[k+5]));
        }
        float* trow = t + r * TP + 12 * s;
        *reinterpret_cast<float4*>(trow)      = make_float4(o[0].x,o[0].y,o[1].x,o[1].y);
        *reinterpret_cast<float4*>(trow + 4)  = make_float4(o[2].x,o[2].y,o[3].x,o[3].y);
        *reinterpret_cast<float4*>(trow + 8)  = make_float4(o[4].x,o[4].y,o[5].x,o[5].y);
        *reinterpret_cast<float2*>(trow + 12) = o[6];
    }
    __syncthreads();

    // ---- Stage B: per-column vertical up + lrelu + down-V fused in registers.
    // 74 cols x 2 row-segments (16 outputs each). Update to acc_i at step k
    // feeds the output stored at step k+i; guard 5 <= k+i <= 20 (compile-time).
    if (tid < 148) {
        const int seg = (tid >= 74) ? 1 : 0;
        const int j   = tid - 74 * seg;
        const int mb  = seg << 4;                  // 0 or 16
        const float* tc = t + mb * TP + j;
        float win[26];
#pragma unroll
        for (int i = 0; i < 26; i++) win[i] = tc[i * TP];
        float acc0 = 0.f, acc1 = 0.f, acc2 = 0.f, acc3 = 0.f, acc4 = 0.f, acc5 = 0.f;
        float* wc = w + j;
#pragma unroll
        for (int k = 0; k < 21; k++) {
            float ze = UP_E(win[k],win[k+1],win[k+2],win[k+3],win[k+4],win[k+5]);
            float zo = UP_O(win[k],win[k+1],win[k+2],win[k+3],win[k+4],win[k+5]);
            ze = fmaxf(ze, 0.01f * ze);            // lrelu (exact for this range)
            zo = fmaxf(zo, 0.01f * zo);
            if (k >= 5)            acc0 = fmaf(e1, ze, fmaf(e0, zo, acc0));
            if (k >= 4 && k <= 19) acc1 = fmaf(e3, ze, fmaf(e2, zo, acc1));
            if (k >= 3 && k <= 18) acc2 = fmaf(e5, ze, fmaf(e4, zo, acc2));
            if (k >= 2 && k <= 17) acc3 = fmaf(e4, ze, fmaf(e5, zo, acc3));
            if (k >= 1 && k <= 16) acc4 = fmaf(e2, ze, fmaf(e3, zo, acc4));
            if (k <= 15)           acc5 = fmaf(e0, ze, e1 * zo);
            if (k >= 5) wc[(mb + k - 5) * WP] = acc0;
            acc0 = acc1; acc1 = acc2; acc2 = acc3; acc3 = acc4; acc4 = acc5;
        }
    }
    __syncthreads();

    // ---- Stage C: horizontal down + store. Thread (m, s) computes out cols
    // 4s..4s+3 of row m from w[m][8s..8s+17] (5 LDS.128), float4 store.
    {
        const int m = tid >> 3, s = tid & 7;
        const float4* wr = reinterpret_cast<const float4*>(w + m * WP) + 2 * s;
        float4 q0 = wr[0], q1 = wr[1], q2 = wr[2], q3 = wr[3], q4 = wr[4];
        float v0=q0.x,v1=q0.y,v2=q0.z,v3=q0.w,
              v4=q1.x,v5=q1.y,v6=q1.z,v7=q1.w,
              v8=q2.x,v9=q2.y,v10=q2.z,v11=q2.w,
              v12=q3.x,v13=q3.y,v14=q3.z,v15=q3.w,
              v16=q4.x,v17=q4.y;
        float o0 = DN(v0,v1,v2,v3,v4,v5,v6,v7,v8,v9,v10,v11);
        float o1 = DN(v2,v3,v4,v5,v6,v7,v8,v9,v10,v11,v12,v13);
        float o2 = DN(v4,v5,v6,v7,v8,v9,v10,v11,v12,v13,v14,v15);
        float o3 = DN(v6,v7,v8,v9,v10,v11,v12,v13,v14,v15,v16,v17);
        float* od = out + (size_t)ch * OW * OW + (size_t)(m0 + m) * OW + n0 + 4 * s;
        *reinterpret_cast<float4*>(od) = make_float4(o0, o1, o2, o3);
    }
}

extern "C" void kernel_launch(void* const* d_in, const int* in_sizes, int n_in,
                              void* d_out, int out_size) {
    const float* x   = (const float*)d_in[0];
    const float* fup = (const float*)d_in[1];
    const float* fdn = (const float*)d_in[2];
    float* out = (float*)d_out;
    dim3 grid(16, 1024);
    flrelu_fused_kernel<<<grid, NTHREADS>>>(x, fup, fdn, out);
}

// round 13
// speedup vs baseline: 1.4712x; 1.0556x over previous
#include <cuda_runtime.h>

// Fused filtered-lrelu: up-H from gmem (LDG.64) -> per-column up-V + lrelu +
// down-V fused in registers with f32x2 packing over the (even,odd) phase pair
// -> down-H. x: [1024,130,130] f32 -> out: [1024,128,128] f32.

#define IH 130
#define IW 130
#define OW 128
#define TP 80      // t tile stride (42 rows x 74 cols), mult of 4 for STS.128
#define WP 76      // w tile stride (32 rows x 74 cols), mult of 4
#define NTHREADS 256

// scalar up-pair (stage A): 6 unique symmetric taps g0..g5
#define UP_E(w0,w1,w2,w3,w4,w5) \
    fmaf(g0,(w5), fmaf(g2,(w4), fmaf(g4,(w3), fmaf(g5,(w2), fmaf(g3,(w1), g1*(w0))))))
#define UP_O(w0,w1,w2,w3,w4,w5) \
    fmaf(g1,(w5), fmaf(g3,(w4), fmaf(g5,(w3), fmaf(g4,(w2), fmaf(g2,(w1), g0*(w0))))))
// 12-tap symmetric down filter over v0..v11:
#define DN(v0,v1,v2,v3,v4,v5,v6,v7,v8,v9,v10,v11) \
    fmaf(e0,(v11), fmaf(e1,(v10), fmaf(e2,(v9), fmaf(e3,(v8), fmaf(e4,(v7), \
    fmaf(e5,(v6),  fmaf(e5,(v5),  fmaf(e4,(v4), fmaf(e3,(v3), fmaf(e2,(v2), \
    fmaf(e1,(v1),  e0*(v0))))))))))))

__device__ __forceinline__ float2 ffma2(float2 a, float2 b, float2 c) {
    float2 d;
    asm("{\n\t.reg .b64 A,B,C,D;\n\t"
        "mov.b64 A,{%2,%3};\n\tmov.b64 B,{%4,%5};\n\tmov.b64 C,{%6,%7};\n\t"
        "fma.rn.f32x2 D,A,B,C;\n\t"
        "mov.b64 {%0,%1},D;\n\t}"
        : "=f"(d.x), "=f"(d.y)
        : "f"(a.x), "f"(a.y), "f"(b.x), "f"(b.y), "f"(c.x), "f"(c.y));
    return d;
}
__device__ __forceinline__ float2 fmul2(float2 a, float2 b) {
    float2 d;
    asm("{\n\t.reg .b64 A,B,D;\n\t"
        "mov.b64 A,{%2,%3};\n\tmov.b64 B,{%4,%5};\n\t"
        "mul.rn.f32x2 D,A,B;\n\t"
        "mov.b64 {%0,%1},D;\n\t}"
        : "=f"(d.x), "=f"(d.y)
        : "f"(a.x), "f"(a.y), "f"(b.x), "f"(b.y));
    return d;
}

__global__ __launch_bounds__(NTHREADS)
void flrelu_fused_kernel(const float* __restrict__ x,
                         const float* __restrict__ fup,
                         const float* __restrict__ fdn,
                         float* __restrict__ out)
{
    __shared__ __align__(16) float t[42 * TP];   // 13.4 KB
    __shared__ __align__(16) float w[32 * WP];   //  9.7 KB

    const float g0 = fup[0] * 2.0f, g1 = fup[1] * 2.0f, g2 = fup[2] * 2.0f,
                g3 = fup[3] * 2.0f, g4 = fup[4] * 2.0f, g5 = fup[5] * 2.0f;
    const float e0 = fdn[0], e1 = fdn[1], e2 = fdn[2],
                e3 = fdn[3], e4 = fdn[4], e5 = fdn[5];

    const int tile = blockIdx.x;
    const int ch   = blockIdx.y;
    const int m0   = (tile >> 2) * 32;
    const int n0   = (tile & 3) * 32;
    const int tid  = threadIdx.x;

    // ---- Stage A: horizontal 2x-up from gmem with float2 loads (unchanged).
    if (tid < 252) {
        const int r = tid / 6, s = tid - 6 * (tid / 6);
        const int gr  = m0 - 4 + r;
        const int gc0 = n0 - 4 + 6 * s;            // always even
        const bool rok = (unsigned)gr < (unsigned)IH;
        const float2* xrow2 = reinterpret_cast<const float2*>(
            x + (size_t)ch * IH * IW + (size_t)gr * IW + gc0);
        float xa[14];
        if (n0 == 32 || n0 == 64) {                // interior: row predicate only
#pragma unroll
            for (int p = 0; p < 7; p++) {
                float2 v = rok ? xrow2[p] : make_float2(0.f, 0.f);
                xa[2 * p] = v.x; xa[2 * p + 1] = v.y;
            }
        } else {
#pragma unroll
            for (int p = 0; p < 7; p++) {
                bool ok = rok && ((unsigned)(gc0 + 2 * p) < (unsigned)IW);
                float2 v = ok ? xrow2[p] : make_float2(0.f, 0.f);
                xa[2 * p] = v.x; xa[2 * p + 1] = v.y;
            }
        }
        float2 o[7];
#pragma unroll
        for (int k = 0; k < 7; k++) {
            o[k] = make_float2(UP_E(xa[k],xa[k+1],xa[k+2],xa[k+3],xa[k+4],xa[k+5]),
                               UP_O(xa[k],xa[k+1],xa[k+2],xa[k+3],xa[k+4],xa[k+5]));
        }
        float* trow = t + r * TP + 12 * s;
        *reinterpret_cast<float4*>(trow)      = make_float4(o[0].x,o[0].y,o[1].x,o[1].y);
        *reinterpret_cast<float4*>(trow + 4)  = make_float4(o[2].x,o[2].y,o[3].x,o[3].y);
        *reinterpret_cast<float4*>(trow + 8)  = make_float4(o[4].x,o[4].y,o[5].x,o[5].y);
        *reinterpret_cast<float2*>(trow + 12) = o[6];
    }
    __syncthreads();

    // ---- Stage B: per-column up-V + lrelu + down-V, f32x2 over (ze,zo).
    // 74 cols x 2 row-segments (16 outputs each). Sliding dup-packed window
    // (6 slots, compile-time modular index). Accumulators stay packed per
    // phase; horizontal add at store. Guards: acc_i live iff 5 <= k+i <= 20.
    if (tid < 148) {
        const int seg = (tid >= 74) ? 1 : 0;
        const int j   = tid - 74 * seg;
        const int mb  = seg << 4;                  // 0 or 16
        const float* tc = t + mb * TP + j;
        // packed up-taps (E_p, O_p) and down-taps (e_hi, e_lo) per acc
        const float2 P0 = make_float2(g1, g0), P1 = make_float2(g3, g2),
                     P2 = make_float2(g5, g4), P3 = make_float2(g4, g5),
                     P4 = make_float2(g2, g3), P5 = make_float2(g0, g1);
        const float2 ED0 = make_float2(e1, e0), ED1 = make_float2(e3, e2),
                     ED2 = make_float2(e5, e4), ED3 = make_float2(e4, e5),
                     ED4 = make_float2(e2, e3), ED5 = make_float2(e0, e1);
        float2 wb[6];
#pragma unroll
        for (int i = 0; i < 6; i++) {
            float v = tc[i * TP];
            wb[i] = make_float2(v, v);
        }
        float2 acc0 = make_float2(0.f, 0.f), acc1 = acc0, acc2 = acc0,
               acc3 = acc0, acc4 = acc0, acc5 = acc0;
        float* wc = w + j;
#pragma unroll
        for (int k = 0; k < 21; k++) {
            float2 zz = fmul2(P0, wb[k % 6]);
            zz = ffma2(P1, wb[(k + 1) % 6], zz);
            zz = ffma2(P2, wb[(k + 2) % 6], zz);
            zz = ffma2(P3, wb[(k + 3) % 6], zz);
            zz = ffma2(P4, wb[(k + 4) % 6], zz);
            zz = ffma2(P5, wb[(k + 5) % 6], zz);
            zz.x = fmaxf(zz.x, 0.01f * zz.x);      // lrelu on the two halves
            zz.y = fmaxf(zz.y, 0.01f * zz.y);
            if (k >= 5)            acc0 = ffma2(ED0, zz, acc0);
            if (k >= 4 && k <= 19) acc1 = ffma2(ED1, zz, acc1);
            if (k >= 3 && k <= 18) acc2 = ffma2(ED2, zz, acc2);
            if (k >= 2 && k <= 17) acc3 = ffma2(ED3, zz, acc3);
            if (k >= 1 && k <= 16) acc4 = ffma2(ED4, zz, acc4);
            if (k >= 5) wc[(mb + k - 5) * WP] = acc0.x + acc0.y;
            acc0 = acc1; acc1 = acc2; acc2 = acc3; acc3 = acc4;
            if (k <= 15) acc4 = fmul2(ED5, zz);    // fresh tail accumulator
            if (k <= 19) {                         // slide: load row k+6
                float v = tc[(k + 6) * TP];
                wb[k % 6] = make_float2(v, v);
            }
        }
    }
    __syncthreads();

    // ---- Stage C: horizontal down + store (unchanged).
    {
        const int m = tid >> 3, s = tid & 7;
        const float4* wr = reinterpret_cast<const float4*>(w + m * WP) + 2 * s;
        float4 q0 = wr[0], q1 = wr[1], q2 = wr[2], q3 = wr[3], q4 = wr[4];
        float v0=q0.x,v1=q0.y,v2=q0.z,v3=q0.w,
              v4=q1.x,v5=q1.y,v6=q1.z,v7=q1.w,
              v8=q2.x,v9=q2.y,v10=q2.z,v11=q2.w,
              v12=q3.x,v13=q3.y,v14=q3.z,v15=q3.w,
              v16=q4.x,v17=q4.y;
        float o0 = DN(v0,v1,v2,v3,v4,v5,v6,v7,v8,v9,v10,v11);
        float o1 = DN(v2,v3,v4,v5,v6,v7,v8,v9,v10,v11,v12,v13);
        float o2 = DN(v4,v5,v6,v7,v8,v9,v10,v11,v12,v13,v14,v15);
        float o3 = DN(v6,v7,v8,v9,v10,v11,v12,v13,v14,v15,v16,v17);
        float* od = out + (size_t)ch * OW * OW + (size_t)(m0 + m) * OW + n0 + 4 * s;
        *reinterpret_cast<float4*>(od) = make_float4(o0, o1, o2, o3);
    }
}

extern "C" void kernel_launch(void* const* d_in, const int* in_sizes, int n_in,
                              void* d_out, int out_size) {
    const float* x   = (const float*)d_in[0];
    const float* fup = (const float*)d_in[1];
    const float* fdn = (const float*)d_in[2];
    float* out = (float*)d_out;
    dim3 grid(16, 1024);
    flrelu_fused_kernel<<<grid, NTHREADS>>>(x, fup, fdn, out);
}